// round 4
// baseline (speedup 1.0000x reference)
#include <cuda_runtime.h>

// Problem-fixed maxima (sizes derived at launch from in_sizes, bounded by these)
#define MAX_NE 50048
#define MAX_NR 1024
#define MAX_E  800000
#define EH 256
#define RH 64

// -------- scratch (device globals; no allocation allowed) --------
__device__ float    g_seh[MAX_NE];
__device__ float    g_set[MAX_NE];
__device__ float    g_sr [MAX_NR];
__device__ unsigned g_maxh[MAX_NE];
__device__ unsigned g_maxt[MAX_NE];
__device__ float    g_denh[MAX_NE];
__device__ float    g_dent[MAX_NE];
__device__ float    g_exh[MAX_E];
__device__ float    g_ext[MAX_E];

// Order-preserving float<->uint mapping so atomicMax(unsigned) == float max.
__device__ __forceinline__ unsigned enc_f(float f) {
    unsigned u = __float_as_uint(f);
    return (u & 0x80000000u) ? ~u : (u | 0x80000000u);
}
__device__ __forceinline__ float dec_f(unsigned u) {
    u = (u & 0x80000000u) ? (u & 0x7FFFFFFFu) : ~u;
    return __uint_as_float(u);
}

__device__ __forceinline__ float leaky(float x) {
    return x > 0.f ? x : 0.01f * x;
}

// ---------------- K0: init scratch ----------------
__global__ void k_init(int n_nodes) {
    int i = blockIdx.x * blockDim.x + threadIdx.x;
    if (i < n_nodes) {
        g_maxh[i] = 0u;   // < enc(anything finite): safe identity for max
        g_maxt[i] = 0u;
        g_denh[i] = 0.f;
        g_dent[i] = 0.f;
    }
}

// ---------------- K1: per-node scores (warp per node) ----------------
__global__ void k_node_scores(const float* __restrict__ xe,
                              const float* __restrict__ ah,
                              const float* __restrict__ at, int n) {
    int warp = (blockIdx.x * blockDim.x + threadIdx.x) >> 5;
    int lane = threadIdx.x & 31;
    if (warp >= n) return;
    const float* row = xe + (size_t)warp * EH;
    float sh = 0.f, st = 0.f;
#pragma unroll
    for (int j = 0; j < EH / 32; j++) {
        float v = row[lane + 32 * j];
        sh = fmaf(v, ah[lane + 32 * j], sh);
        st = fmaf(v, at[lane + 32 * j], st);
    }
#pragma unroll
    for (int o = 16; o; o >>= 1) {
        sh += __shfl_xor_sync(0xFFFFFFFFu, sh, o);
        st += __shfl_xor_sync(0xFFFFFFFFu, st, o);
    }
    if (lane == 0) { g_seh[warp] = sh; g_set[warp] = st; }
}

// ---------------- K2: per-relation scores (warp per rel) ----------------
__global__ void k_rel_scores(const float* __restrict__ xr,
                             const float* __restrict__ ar, int nr) {
    int warp = (blockIdx.x * blockDim.x + threadIdx.x) >> 5;
    int lane = threadIdx.x & 31;
    if (warp >= nr) return;
    const float* row = xr + (size_t)warp * RH;
    float s = fmaf(row[lane], ar[lane], row[lane + 32] * ar[lane + 32]);
#pragma unroll
    for (int o = 16; o; o >>= 1) s += __shfl_xor_sync(0xFFFFFFFFu, s, o);
    if (lane == 0) g_sr[warp] = s;
}

// ---------------- K3: segment max over edges ----------------
__global__ void k_edge_max(const int* __restrict__ ei,
                           const int* __restrict__ rel, int E) {
    int e = blockIdx.x * blockDim.x + threadIdx.x;
    if (e >= E) return;
    int h = ei[e];
    int t = ei[E + e];
    int r = rel[e];
    float sr = g_sr[r];
    float lh = leaky(g_seh[h] + sr);
    float lt = leaky(g_set[t] + sr);
    atomicMax(&g_maxh[h], enc_f(lh));
    atomicMax(&g_maxt[t], enc_f(lt));
}

// ---------------- K4: exp + segment denominators ----------------
__global__ void k_edge_exp(const int* __restrict__ ei,
                           const int* __restrict__ rel, int E) {
    int e = blockIdx.x * blockDim.x + threadIdx.x;
    if (e >= E) return;
    int h = ei[e];
    int t = ei[E + e];
    int r = rel[e];
    float sr = g_sr[r];
    float lh = leaky(g_seh[h] + sr);
    float lt = leaky(g_set[t] + sr);
    float exh = expf(lh - dec_f(g_maxh[h]));
    float ext = expf(lt - dec_f(g_maxt[t]));
    g_exh[e] = exh;
    g_ext[e] = ext;
    atomicAdd(&g_denh[h], exh);
    atomicAdd(&g_dent[t], ext);
}

// ---------------- K5: scatter alpha * x_r[rel] with vectorized RED ----------------
__device__ __forceinline__ void red_add_v4(float* p, float4 v) {
    asm volatile("red.global.add.v4.f32 [%0], {%1, %2, %3, %4};"
                 :: "l"(p), "f"(v.x), "f"(v.y), "f"(v.z), "f"(v.w)
                 : "memory");
}

__global__ void k_scatter(const int* __restrict__ ei,
                          const int* __restrict__ rel,
                          const float* __restrict__ xr,
                          float* __restrict__ out, int E) {
    int gid = blockIdx.x * blockDim.x + threadIdx.x;
    int e = gid >> 4;        // 16 lanes per edge (4 floats each = 64 dims)
    int k = gid & 15;
    if (e >= E) return;
    int h = ei[e];
    int t = ei[E + e];
    int r = rel[e];
    float a_h = g_exh[e] / (g_denh[h] + 1e-16f);
    float a_t = g_ext[e] / (g_dent[t] + 1e-16f);
    float4 m = reinterpret_cast<const float4*>(xr + (size_t)r * RH)[k];
    float4 vh = make_float4(m.x * a_h, m.y * a_h, m.z * a_h, m.w * a_h);
    float4 vt = make_float4(m.x * a_t, m.y * a_t, m.z * a_t, m.w * a_t);
    red_add_v4(out + (size_t)h * (2 * RH) + k * 4, vh);
    red_add_v4(out + (size_t)t * (2 * RH) + RH + k * 4, vt);
}

// ---------------- launch ----------------
extern "C" void kernel_launch(void* const* d_in, const int* in_sizes, int n_in,
                              void* d_out, int out_size) {
    const float* xe  = (const float*)d_in[0];
    const float* xr  = (const float*)d_in[1];
    const int*   ei  = (const int*)d_in[2];   // int32 (JAX x64 disabled)
    const int*   rel = (const int*)d_in[3];
    // d_in[4], d_in[5] (line graph) unused by the reference output
    const float* ahw = (const float*)d_in[6];
    const float* atw = (const float*)d_in[7];
    const float* arw = (const float*)d_in[8];

    int nE = in_sizes[0] / EH;   // 50000
    int nR = in_sizes[1] / RH;   // 1000
    int E  = in_sizes[3];        // 800000
    if (nE > MAX_NE) nE = MAX_NE;
    if (nR > MAX_NR) nR = MAX_NR;
    if (E  > MAX_E)  E  = MAX_E;

    float* out = (float*)d_out;

    cudaMemsetAsync(d_out, 0, (size_t)out_size * sizeof(float), 0);
    k_init<<<(nE + 255) / 256, 256>>>(nE);
    k_node_scores<<<(nE + 7) / 8, 256>>>(xe, ahw, atw, nE);
    k_rel_scores<<<(nR + 7) / 8, 256>>>(xr, arw, nR);
    k_edge_max<<<(E + 255) / 256, 256>>>(ei, rel, E);
    k_edge_exp<<<(E + 255) / 256, 256>>>(ei, rel, E);
    int scatter_threads = E * 16;
    k_scatter<<<(scatter_threads + 255) / 256, 256>>>(ei, rel, xr, out, E);
}

// round 5
// speedup vs baseline: 1.2522x; 1.2522x over previous
#include <cuda_runtime.h>

#define MAX_NE 50048
#define MAX_NR 1024
#define MAX_E  800000
#define EH 256
#define RH 64
#define SCAN_B 512

// -------- scratch (device globals; no allocation allowed) --------
__device__ float    g_seh[MAX_NE];
__device__ float    g_set[MAX_NE];
__device__ float    g_sr [MAX_NR];
__device__ unsigned g_Menc;            // encoded max over s_r
__device__ float    g_denh[MAX_NE];
__device__ float    g_dent[MAX_NE];
__device__ float    g_invh[MAX_NE];
__device__ float    g_invt[MAX_NE];
__device__ int      g_cnth[MAX_NE];
__device__ int      g_cntt[MAX_NE];
__device__ int      g_offh[MAX_NE];
__device__ int      g_offt[MAX_NE];
__device__ int      g_curh[MAX_NE];
__device__ int      g_curt[MAX_NE];
__device__ int      g_bsumh[SCAN_B];
__device__ int      g_bsumt[SCAN_B];
__device__ int      g_boffh[SCAN_B];
__device__ int      g_bofft[SCAN_B];
__device__ float    g_exh[MAX_E];
__device__ float    g_ext[MAX_E];
__device__ int2     g_adjh[MAX_E];     // (rel, alpha bits) per CSR slot, head-sorted
__device__ int2     g_adjt[MAX_E];     // tail-sorted

// Order-preserving float<->uint map so atomicMax(unsigned) == float max.
__device__ __forceinline__ unsigned enc_f(float f) {
    unsigned u = __float_as_uint(f);
    return (u & 0x80000000u) ? ~u : (u | 0x80000000u);
}
__device__ __forceinline__ float dec_f(unsigned u) {
    u = (u & 0x80000000u) ? (u & 0x7FFFFFFFu) : ~u;
    return __uint_as_float(u);
}
__device__ __forceinline__ float leaky(float x) { return x > 0.f ? x : 0.01f * x; }

// ---------------- K0: init ----------------
__global__ void k_init(int nE) {
    int i = blockIdx.x * blockDim.x + threadIdx.x;
    if (i == 0) g_Menc = 0u;  // < enc(any float)
    if (i < nE) {
        g_denh[i] = 0.f; g_dent[i] = 0.f;
        g_cnth[i] = 0;   g_cntt[i] = 0;
    }
}

// ---------------- K1: node scores + rel scores + max(s_r), fused ----------------
__global__ void k_scores(const float* __restrict__ xe,
                         const float* __restrict__ xr,
                         const float* __restrict__ ah,
                         const float* __restrict__ at,
                         const float* __restrict__ ar,
                         int nE, int nR, int nodeBlocks) {
    int b = blockIdx.x;
    int lane = threadIdx.x & 31;
    int warpInBlk = threadIdx.x >> 5;
    if (b < nodeBlocks) {
        int n = b * 8 + warpInBlk;
        if (n >= nE) return;
        const float* row = xe + (size_t)n * EH;
        float sh = 0.f, st = 0.f;
#pragma unroll
        for (int j = 0; j < EH / 32; j++) {
            float v = row[lane + 32 * j];
            sh = fmaf(v, ah[lane + 32 * j], sh);
            st = fmaf(v, at[lane + 32 * j], st);
        }
#pragma unroll
        for (int o = 16; o; o >>= 1) {
            sh += __shfl_xor_sync(0xFFFFFFFFu, sh, o);
            st += __shfl_xor_sync(0xFFFFFFFFu, st, o);
        }
        if (lane == 0) { g_seh[n] = sh; g_set[n] = st; }
    } else {
        int r = (b - nodeBlocks) * 8 + warpInBlk;
        if (r >= nR) return;
        const float* row = xr + (size_t)r * RH;
        float s = fmaf(row[lane], ar[lane], row[lane + 32] * ar[lane + 32]);
#pragma unroll
        for (int o = 16; o; o >>= 1) s += __shfl_xor_sync(0xFFFFFFFFu, s, o);
        if (lane == 0) {
            g_sr[r] = s;
            atomicMax(&g_Menc, enc_f(s));
        }
    }
}

// ---------------- K2: per-edge exp (bound-stabilized) + denominators + histogram ----------------
__global__ void k_edge(const int* __restrict__ ei,
                       const int* __restrict__ rel, int E) {
    int e = blockIdx.x * blockDim.x + threadIdx.x;
    if (e >= E) return;
    int h = ei[e];
    int t = ei[E + e];
    int r = rel[e];
    float sr = g_sr[r];
    float M = dec_f(g_Menc);
    float sh = g_seh[h], st = g_set[t];
    // B = leaky(s + M) >= leaky(s + sr) for all sr (monotone); exp arg <= 0.
    float exh = __expf(leaky(sh + sr) - leaky(sh + M));
    float ext = __expf(leaky(st + sr) - leaky(st + M));
    g_exh[e] = exh;
    g_ext[e] = ext;
    atomicAdd(&g_denh[h], exh);
    atomicAdd(&g_dent[t], ext);
    atomicAdd(&g_cnth[h], 1);
    atomicAdd(&g_cntt[t], 1);
}

// ---------------- K3: block-level exclusive scan of counts ----------------
__global__ void k_scan1(int nE) {
    __shared__ int s[SCAN_B];
    int t = threadIdx.x;
    int i = blockIdx.x * SCAN_B + t;
    // head
    int v = (i < nE) ? g_cnth[i] : 0;
    s[t] = v; __syncthreads();
    for (int d = 1; d < SCAN_B; d <<= 1) {
        int x = (t >= d) ? s[t - d] : 0;
        __syncthreads();
        s[t] += x;
        __syncthreads();
    }
    if (i < nE) g_offh[i] = s[t] - v;
    if (t == SCAN_B - 1) g_bsumh[blockIdx.x] = s[t];
    __syncthreads();
    // tail
    v = (i < nE) ? g_cntt[i] : 0;
    s[t] = v; __syncthreads();
    for (int d = 1; d < SCAN_B; d <<= 1) {
        int x = (t >= d) ? s[t - d] : 0;
        __syncthreads();
        s[t] += x;
        __syncthreads();
    }
    if (i < nE) g_offt[i] = s[t] - v;
    if (t == SCAN_B - 1) g_bsumt[blockIdx.x] = s[t];
}

// ---------------- K4: scan of block sums (single block) ----------------
__global__ void k_scan2(int nB) {
    __shared__ int s[SCAN_B];
    int t = threadIdx.x;
    int v = (t < nB) ? g_bsumh[t] : 0;
    s[t] = v; __syncthreads();
    for (int d = 1; d < SCAN_B; d <<= 1) {
        int x = (t >= d) ? s[t - d] : 0;
        __syncthreads();
        s[t] += x;
        __syncthreads();
    }
    if (t < nB) g_boffh[t] = s[t] - v;
    __syncthreads();
    v = (t < nB) ? g_bsumt[t] : 0;
    s[t] = v; __syncthreads();
    for (int d = 1; d < SCAN_B; d <<= 1) {
        int x = (t >= d) ? s[t - d] : 0;
        __syncthreads();
        s[t] += x;
        __syncthreads();
    }
    if (t < nB) g_bofft[t] = s[t] - v;
}

// ---------------- K5: add block offsets, set fill cursors, reciprocal denominators ----------------
__global__ void k_scan3(int nE) {
    int i = blockIdx.x * blockDim.x + threadIdx.x;
    if (i >= nE) return;
    int blk = i / SCAN_B;
    int oh = g_offh[i] + g_boffh[blk];
    int ot = g_offt[i] + g_bofft[blk];
    g_offh[i] = oh; g_curh[i] = oh;
    g_offt[i] = ot; g_curt[i] = ot;
    // No +1e-16: bound-stabilized den may be tiny; ratio is exact (ref's eps is negligible there).
    g_invh[i] = 1.0f / g_denh[i];   // inf for isolated nodes, never used
    g_invt[i] = 1.0f / g_dent[i];
}

// ---------------- K6: fill CSR slots with (rel, alpha) ----------------
__global__ void k_fill(const int* __restrict__ ei,
                       const int* __restrict__ rel, int E) {
    int e = blockIdx.x * blockDim.x + threadIdx.x;
    if (e >= E) return;
    int h = ei[e];
    int t = ei[E + e];
    int r = rel[e];
    float a_h = g_exh[e] * g_invh[h];
    float a_t = g_ext[e] * g_invt[t];
    int p = atomicAdd(&g_curh[h], 1);
    g_adjh[p] = make_int2(r, __float_as_int(a_h));
    int q = atomicAdd(&g_curt[t], 1);
    g_adjt[q] = make_int2(r, __float_as_int(a_t));
}

// ---------------- K7: warp-per-node gather, atomic-free output ----------------
__global__ void k_gather(const float* __restrict__ xr,
                         float* __restrict__ out, int nE) {
    int n = (blockIdx.x * blockDim.x + threadIdx.x) >> 5;
    int lane = threadIdx.x & 31;
    if (n >= nE) return;

    float2 acch = make_float2(0.f, 0.f);
    float2 acct = make_float2(0.f, 0.f);

    int degh = g_cnth[n], bh = g_offh[n];
#pragma unroll 4
    for (int j = 0; j < degh; j++) {
        int2 arp = g_adjh[bh + j];                    // broadcast load
        float w = __int_as_float(arp.y);
        float2 m = *reinterpret_cast<const float2*>(xr + (size_t)arp.x * RH + lane * 2);
        acch.x = fmaf(w, m.x, acch.x);
        acch.y = fmaf(w, m.y, acch.y);
    }
    int degt = g_cntt[n], bt = g_offt[n];
#pragma unroll 4
    for (int j = 0; j < degt; j++) {
        int2 arp = g_adjt[bt + j];
        float w = __int_as_float(arp.y);
        float2 m = *reinterpret_cast<const float2*>(xr + (size_t)arp.x * RH + lane * 2);
        acct.x = fmaf(w, m.x, acct.x);
        acct.y = fmaf(w, m.y, acct.y);
    }

    float2* o = reinterpret_cast<float2*>(out + (size_t)n * (2 * RH));
    o[lane] = acch;        // dims [0,64)
    o[32 + lane] = acct;   // dims [64,128)
}

// ---------------- launch ----------------
extern "C" void kernel_launch(void* const* d_in, const int* in_sizes, int n_in,
                              void* d_out, int out_size) {
    const float* xe  = (const float*)d_in[0];
    const float* xr  = (const float*)d_in[1];
    const int*   ei  = (const int*)d_in[2];   // int32 (JAX x64 disabled)
    const int*   rel = (const int*)d_in[3];
    // d_in[4], d_in[5] (line graph) unused by the reference output
    const float* ahw = (const float*)d_in[6];
    const float* atw = (const float*)d_in[7];
    const float* arw = (const float*)d_in[8];

    int nE = in_sizes[0] / EH;   // 50000
    int nR = in_sizes[1] / RH;   // 1000
    int E  = in_sizes[3];        // 800000
    if (nE > MAX_NE) nE = MAX_NE;
    if (nR > MAX_NR) nR = MAX_NR;
    if (E  > MAX_E)  E  = MAX_E;

    float* out = (float*)d_out;

    int nodeBlocks = (nE + 7) / 8;
    int relBlocks  = (nR + 7) / 8;
    int nB = (nE + SCAN_B - 1) / SCAN_B;   // 98 <= SCAN_B

    k_init<<<(nE + 255) / 256, 256>>>(nE);
    k_scores<<<nodeBlocks + relBlocks, 256>>>(xe, xr, ahw, atw, arw, nE, nR, nodeBlocks);
    k_edge<<<(E + 255) / 256, 256>>>(ei, rel, E);
    k_scan1<<<nB, SCAN_B>>>(nE);
    k_scan2<<<1, SCAN_B>>>(nB);
    k_scan3<<<(nE + 255) / 256, 256>>>(nE);
    k_fill<<<(E + 255) / 256, 256>>>(ei, rel, E);
    k_gather<<<(nE + 7) / 8, 256>>>(xr, out, nE);
}

// round 6
// speedup vs baseline: 1.4317x; 1.1433x over previous
#include <cuda_runtime.h>

#define MAX_NE 50048
#define MAX_NR 1024
#define MAX_E  800000
#define EH 256
#define RH 64
#define SCAN_B 512

// -------- scratch (device globals; no allocation allowed) --------
__device__ float    g_seh[MAX_NE];
__device__ float    g_set[MAX_NE];
__device__ float    g_sr [MAX_NR];
__device__ unsigned g_Menc;            // encoded max over s_r
__device__ int      g_cnth[MAX_NE];
__device__ int      g_cntt[MAX_NE];
__device__ int      g_offh[MAX_NE];
__device__ int      g_offt[MAX_NE];
__device__ int      g_curh[MAX_NE];
__device__ int      g_curt[MAX_NE];
__device__ int      g_bsumh[SCAN_B];
__device__ int      g_bsumt[SCAN_B];
__device__ int      g_boffh[SCAN_B];
__device__ int      g_bofft[SCAN_B];
__device__ int2     g_adjh[MAX_E];     // (rel, ex bits) per CSR slot, head-sorted
__device__ int2     g_adjt[MAX_E];     // tail-sorted

// Order-preserving float<->uint map so atomicMax(unsigned) == float max.
__device__ __forceinline__ unsigned enc_f(float f) {
    unsigned u = __float_as_uint(f);
    return (u & 0x80000000u) ? ~u : (u | 0x80000000u);
}
__device__ __forceinline__ float dec_f(unsigned u) {
    u = (u & 0x80000000u) ? (u & 0x7FFFFFFFu) : ~u;
    return __uint_as_float(u);
}
__device__ __forceinline__ float leaky(float x) { return x > 0.f ? x : 0.01f * x; }

// ---------------- K0: init (zero counts) ----------------
__global__ void k_init(int nE) {
    int i = blockIdx.x * blockDim.x + threadIdx.x;
    if (i == 0) g_Menc = 0u;  // < enc(any float)
    if (i < nE) { g_cnth[i] = 0; g_cntt[i] = 0; }
}

// ---------------- K1: node scores + rel scores + edge histogram, fused ----------------
__global__ void k_phase1(const float* __restrict__ xe,
                         const float* __restrict__ xr,
                         const float* __restrict__ ah,
                         const float* __restrict__ at,
                         const float* __restrict__ ar,
                         const int* __restrict__ ei,
                         int nE, int nR, int E,
                         int nodeBlocks, int relBlocks) {
    int b = blockIdx.x;
    int lane = threadIdx.x & 31;
    int warpInBlk = threadIdx.x >> 5;
    if (b < nodeBlocks) {
        // --- per-node scores: warp per node, float4 loads ---
        int n = b * 8 + warpInBlk;
        if (n >= nE) return;
        const float4* row = reinterpret_cast<const float4*>(xe + (size_t)n * EH);
        const float4* a4h = reinterpret_cast<const float4*>(ah);
        const float4* a4t = reinterpret_cast<const float4*>(at);
        float sh = 0.f, st = 0.f;
#pragma unroll
        for (int j = 0; j < 2; j++) {
            float4 v = row[lane + 32 * j];
            float4 wh = a4h[lane + 32 * j];
            float4 wt = a4t[lane + 32 * j];
            sh = fmaf(v.x, wh.x, fmaf(v.y, wh.y, fmaf(v.z, wh.z, fmaf(v.w, wh.w, sh))));
            st = fmaf(v.x, wt.x, fmaf(v.y, wt.y, fmaf(v.z, wt.z, fmaf(v.w, wt.w, st))));
        }
#pragma unroll
        for (int o = 16; o; o >>= 1) {
            sh += __shfl_xor_sync(0xFFFFFFFFu, sh, o);
            st += __shfl_xor_sync(0xFFFFFFFFu, st, o);
        }
        if (lane == 0) { g_seh[n] = sh; g_set[n] = st; }
    } else if (b < nodeBlocks + relBlocks) {
        // --- per-relation scores + global max ---
        int r = (b - nodeBlocks) * 8 + warpInBlk;
        if (r >= nR) return;
        const float* row = xr + (size_t)r * RH;
        float s = fmaf(row[lane], ar[lane], row[lane + 32] * ar[lane + 32]);
#pragma unroll
        for (int o = 16; o; o >>= 1) s += __shfl_xor_sync(0xFFFFFFFFu, s, o);
        if (lane == 0) {
            g_sr[r] = s;
            atomicMax(&g_Menc, enc_f(s));
        }
    } else {
        // --- edge histogram ---
        int e = (b - nodeBlocks - relBlocks) * 256 + threadIdx.x;
        if (e >= E) return;
        atomicAdd(&g_cnth[ei[e]], 1);
        atomicAdd(&g_cntt[ei[E + e]], 1);
    }
}

// ---------------- shuffle-based exclusive block scan helper ----------------
// returns exclusive prefix of v within the block; total written to *tot by caller logic
__device__ __forceinline__ int block_exscan(int v, int* warp_sums, int* p_total) {
    int lane = threadIdx.x & 31;
    int wid = threadIdx.x >> 5;
    int x = v;
#pragma unroll
    for (int o = 1; o < 32; o <<= 1) {
        int y = __shfl_up_sync(0xFFFFFFFFu, x, o);
        if (lane >= o) x += y;
    }
    // x = inclusive scan within warp
    if (lane == 31) warp_sums[wid] = x;
    __syncthreads();
    if (wid == 0) {
        int nw = blockDim.x >> 5;
        int ws = (lane < nw) ? warp_sums[lane] : 0;
#pragma unroll
        for (int o = 1; o < 32; o <<= 1) {
            int y = __shfl_up_sync(0xFFFFFFFFu, ws, o);
            if (lane >= o) ws += y;
        }
        if (lane < nw) warp_sums[lane] = ws;   // inclusive warp sums
        if (lane == (nw - 1)) *p_total = ws;
    }
    __syncthreads();
    int base = (wid > 0) ? warp_sums[wid - 1] : 0;
    return base + x - v;   // exclusive
}

// ---------------- K2: block-level exclusive scan of counts (shuffle) ----------------
__global__ void k_scan1(int nE) {
    __shared__ int wsum[16];
    __shared__ int tot;
    int i = blockIdx.x * SCAN_B + threadIdx.x;
    int v = (i < nE) ? g_cnth[i] : 0;
    int ex = block_exscan(v, wsum, &tot);
    if (i < nE) g_offh[i] = ex;
    if (threadIdx.x == 0) g_bsumh[blockIdx.x] = tot;
    __syncthreads();
    v = (i < nE) ? g_cntt[i] : 0;
    ex = block_exscan(v, wsum, &tot);
    if (i < nE) g_offt[i] = ex;
    if (threadIdx.x == 0) g_bsumt[blockIdx.x] = tot;
}

// ---------------- K3: scan of block sums (single block) ----------------
__global__ void k_scan2(int nB) {
    __shared__ int wsum[16];
    __shared__ int tot;
    int t = threadIdx.x;
    int v = (t < nB) ? g_bsumh[t] : 0;
    int ex = block_exscan(v, wsum, &tot);
    if (t < nB) g_boffh[t] = ex;
    __syncthreads();
    v = (t < nB) ? g_bsumt[t] : 0;
    ex = block_exscan(v, wsum, &tot);
    if (t < nB) g_bofft[t] = ex;
}

// ---------------- K4: add block offsets, set fill cursors ----------------
__global__ void k_scan3(int nE) {
    int i = blockIdx.x * blockDim.x + threadIdx.x;
    if (i >= nE) return;
    int blk = i / SCAN_B;
    int oh = g_offh[i] + g_boffh[blk];
    int ot = g_offt[i] + g_bofft[blk];
    g_offh[i] = oh; g_curh[i] = oh;
    g_offt[i] = ot; g_curt[i] = ot;
}

// ---------------- K5: fill CSR slots with (rel, ex) — exp computed inline ----------------
__global__ void k_fill(const int* __restrict__ ei,
                       const int* __restrict__ rel, int E) {
    int e = blockIdx.x * blockDim.x + threadIdx.x;
    if (e >= E) return;
    int h = ei[e];
    int t = ei[E + e];
    int r = rel[e];
    float sr = g_sr[r];
    float M = dec_f(g_Menc);
    float sh = g_seh[h], st = g_set[t];
    // B(n) = leaky(s_n + M) >= leaky(s_n + sr) for all r (monotone); exp arg <= 0.
    float exh = __expf(leaky(sh + sr) - leaky(sh + M));
    float ext = __expf(leaky(st + sr) - leaky(st + M));
    int p = atomicAdd(&g_curh[h], 1);
    g_adjh[p] = make_int2(r, __float_as_int(exh));
    int q = atomicAdd(&g_curt[t], 1);
    g_adjt[q] = make_int2(r, __float_as_int(ext));
}

// ---------------- K6: warp-per-node gather; denominator accumulated in-register ----------------
__global__ void k_gather(const float* __restrict__ xr,
                         float* __restrict__ out, int nE) {
    int n = (blockIdx.x * blockDim.x + threadIdx.x) >> 5;
    int lane = threadIdx.x & 31;
    if (n >= nE) return;

    float2 acch = make_float2(0.f, 0.f);
    float2 acct = make_float2(0.f, 0.f);
    float denh = 0.f, dent = 0.f;

    int degh = g_cnth[n], bh = g_offh[n];
#pragma unroll 4
    for (int j = 0; j < degh; j++) {
        int2 arp = g_adjh[bh + j];                    // warp-uniform broadcast load
        float w = __int_as_float(arp.y);
        denh += w;                                    // same in every lane
        float2 m = *reinterpret_cast<const float2*>(xr + (size_t)arp.x * RH + lane * 2);
        acch.x = fmaf(w, m.x, acch.x);
        acch.y = fmaf(w, m.y, acch.y);
    }
    int degt = g_cntt[n], bt = g_offt[n];
#pragma unroll 4
    for (int j = 0; j < degt; j++) {
        int2 arp = g_adjt[bt + j];
        float w = __int_as_float(arp.y);
        dent += w;
        float2 m = *reinterpret_cast<const float2*>(xr + (size_t)arp.x * RH + lane * 2);
        acct.x = fmaf(w, m.x, acct.x);
        acct.y = fmaf(w, m.y, acct.y);
    }

    float ih = (denh > 0.f) ? 1.0f / denh : 0.f;
    float it = (dent > 0.f) ? 1.0f / dent : 0.f;
    float2* o = reinterpret_cast<float2*>(out + (size_t)n * (2 * RH));
    o[lane]      = make_float2(acch.x * ih, acch.y * ih);   // dims [0,64)
    o[32 + lane] = make_float2(acct.x * it, acct.y * it);   // dims [64,128)
}

// ---------------- launch ----------------
extern "C" void kernel_launch(void* const* d_in, const int* in_sizes, int n_in,
                              void* d_out, int out_size) {
    const float* xe  = (const float*)d_in[0];
    const float* xr  = (const float*)d_in[1];
    const int*   ei  = (const int*)d_in[2];   // int32 (JAX x64 disabled)
    const int*   rel = (const int*)d_in[3];
    // d_in[4], d_in[5] (line graph) unused by the reference output
    const float* ahw = (const float*)d_in[6];
    const float* atw = (const float*)d_in[7];
    const float* arw = (const float*)d_in[8];

    int nE = in_sizes[0] / EH;   // 50000
    int nR = in_sizes[1] / RH;   // 1000
    int E  = in_sizes[3];        // 800000
    if (nE > MAX_NE) nE = MAX_NE;
    if (nR > MAX_NR) nR = MAX_NR;
    if (E  > MAX_E)  E  = MAX_E;

    float* out = (float*)d_out;

    int nodeBlocks = (nE + 7) / 8;
    int relBlocks  = (nR + 7) / 8;
    int histBlocks = (E + 255) / 256;
    int nB = (nE + SCAN_B - 1) / SCAN_B;   // 98 <= SCAN_B

    k_init<<<(nE + 255) / 256, 256>>>(nE);
    k_phase1<<<nodeBlocks + relBlocks + histBlocks, 256>>>(
        xe, xr, ahw, atw, arw, ei, nE, nR, E, nodeBlocks, relBlocks);
    k_scan1<<<nB, SCAN_B>>>(nE);
    k_scan2<<<1, SCAN_B>>>(nB);
    k_scan3<<<(nE + 255) / 256, 256>>>(nE);
    k_fill<<<(E + 255) / 256, 256>>>(ei, rel, E);
    k_gather<<<(nE + 7) / 8, 256>>>(xr, out, nE);
}

// round 7
// speedup vs baseline: 1.4639x; 1.0225x over previous
#include <cuda_runtime.h>

#define MAX_NE 50048
#define MAX_NR 1024
#define MAX_E  800000
#define EH 256
#define RH 64
#define SCAN_B 512

// -------- scratch (device globals; no allocation allowed) --------
__device__ float    g_seh[MAX_NE];
__device__ float    g_set[MAX_NE];
__device__ float    g_sr [MAX_NR];
__device__ unsigned g_Menc;            // encoded max over s_r
__device__ int      g_arrive;          // grid-barrier arrival counter
__device__ int      g_cnth[MAX_NE];
__device__ int      g_cntt[MAX_NE];
__device__ int      g_offh[MAX_NE];
__device__ int      g_offt[MAX_NE];
__device__ int      g_curh[MAX_NE];
__device__ int      g_curt[MAX_NE];
__device__ int      g_bsumh[SCAN_B];
__device__ int      g_bsumt[SCAN_B];
__device__ int2     g_adjh[MAX_E];     // (rel, ex bits) per CSR slot, head-sorted
__device__ int2     g_adjt[MAX_E];     // tail-sorted

// Order-preserving float<->uint map so atomicMax(unsigned) == float max.
__device__ __forceinline__ unsigned enc_f(float f) {
    unsigned u = __float_as_uint(f);
    return (u & 0x80000000u) ? ~u : (u | 0x80000000u);
}
__device__ __forceinline__ float dec_f(unsigned u) {
    u = (u & 0x80000000u) ? (u & 0x7FFFFFFFu) : ~u;
    return __uint_as_float(u);
}
__device__ __forceinline__ float leaky(float x) { return x > 0.f ? x : 0.01f * x; }

// ---------------- K0: init (zero counts + barrier counter) ----------------
__global__ void k_init(int nE) {
    int i = blockIdx.x * blockDim.x + threadIdx.x;
    if (i == 0) { g_Menc = 0u; g_arrive = 0; }
    if (i < nE) { g_cnth[i] = 0; g_cntt[i] = 0; }
}

// ---------------- K1: node scores + rel scores + edge histogram, fused ----------------
__global__ void k_phase1(const float* __restrict__ xe,
                         const float* __restrict__ xr,
                         const float* __restrict__ ah,
                         const float* __restrict__ at,
                         const float* __restrict__ ar,
                         const int* __restrict__ ei,
                         int nE, int nR, int E,
                         int nodeBlocks, int relBlocks) {
    int b = blockIdx.x;
    int lane = threadIdx.x & 31;
    int warpInBlk = threadIdx.x >> 5;
    if (b < nodeBlocks) {
        // --- per-node scores: warp per node, float4 loads ---
        int n = b * 8 + warpInBlk;
        if (n >= nE) return;
        const float4* row = reinterpret_cast<const float4*>(xe + (size_t)n * EH);
        const float4* a4h = reinterpret_cast<const float4*>(ah);
        const float4* a4t = reinterpret_cast<const float4*>(at);
        float sh = 0.f, st = 0.f;
#pragma unroll
        for (int j = 0; j < 2; j++) {
            float4 v = row[lane + 32 * j];
            float4 wh = a4h[lane + 32 * j];
            float4 wt = a4t[lane + 32 * j];
            sh = fmaf(v.x, wh.x, fmaf(v.y, wh.y, fmaf(v.z, wh.z, fmaf(v.w, wh.w, sh))));
            st = fmaf(v.x, wt.x, fmaf(v.y, wt.y, fmaf(v.z, wt.z, fmaf(v.w, wt.w, st))));
        }
#pragma unroll
        for (int o = 16; o; o >>= 1) {
            sh += __shfl_xor_sync(0xFFFFFFFFu, sh, o);
            st += __shfl_xor_sync(0xFFFFFFFFu, st, o);
        }
        if (lane == 0) { g_seh[n] = sh; g_set[n] = st; }
    } else if (b < nodeBlocks + relBlocks) {
        // --- per-relation scores + global max ---
        int r = (b - nodeBlocks) * 8 + warpInBlk;
        if (r >= nR) return;
        const float* row = xr + (size_t)r * RH;
        float s = fmaf(row[lane], ar[lane], row[lane + 32] * ar[lane + 32]);
#pragma unroll
        for (int o = 16; o; o >>= 1) s += __shfl_xor_sync(0xFFFFFFFFu, s, o);
        if (lane == 0) {
            g_sr[r] = s;
            atomicMax(&g_Menc, enc_f(s));
        }
    } else {
        // --- edge histogram ---
        int e = (b - nodeBlocks - relBlocks) * 256 + threadIdx.x;
        if (e >= E) return;
        atomicAdd(&g_cnth[ei[e]], 1);
        atomicAdd(&g_cntt[ei[E + e]], 1);
    }
}

// ---------------- shuffle-based exclusive block scan helper ----------------
__device__ __forceinline__ int block_exscan(int v, int* warp_sums, int* p_total) {
    int lane = threadIdx.x & 31;
    int wid = threadIdx.x >> 5;
    int x = v;
#pragma unroll
    for (int o = 1; o < 32; o <<= 1) {
        int y = __shfl_up_sync(0xFFFFFFFFu, x, o);
        if (lane >= o) x += y;
    }
    if (lane == 31) warp_sums[wid] = x;
    __syncthreads();
    if (wid == 0) {
        int nw = blockDim.x >> 5;
        int ws = (lane < nw) ? warp_sums[lane] : 0;
#pragma unroll
        for (int o = 1; o < 32; o <<= 1) {
            int y = __shfl_up_sync(0xFFFFFFFFu, ws, o);
            if (lane >= o) ws += y;
        }
        if (lane < nw) warp_sums[lane] = ws;
        if (lane == (nw - 1)) *p_total = ws;
    }
    __syncthreads();
    int base = (wid > 0) ? warp_sums[wid - 1] : 0;
    return base + x - v;
}

// ---------------- K2: fully fused global scan (single launch, grid barrier) ----------------
// All nB (<=98) blocks are co-resident in one wave on 148 SMs -> spin is starvation-free.
__global__ void k_scan(int nE, int nB) {
    __shared__ int wsum[16];
    __shared__ int tot;
    __shared__ int basep[2];
    int b = blockIdx.x;
    int i = b * SCAN_B + threadIdx.x;

    int vh = (i < nE) ? g_cnth[i] : 0;
    int exh = block_exscan(vh, wsum, &tot);
    if (threadIdx.x == 0) g_bsumh[b] = tot;
    __syncthreads();
    int vt = (i < nE) ? g_cntt[i] : 0;
    int ext = block_exscan(vt, wsum, &tot);
    if (threadIdx.x == 0) g_bsumt[b] = tot;

    // grid barrier: make bsums visible, arrive, spin until all arrived
    __threadfence();
    __syncthreads();
    if (threadIdx.x == 0) {
        atomicAdd(&g_arrive, 1);
        while (atomicAdd(&g_arrive, 0) < nB) { }
    }
    __syncthreads();

    // prefix over earlier blocks (<= 98 values, warp 0)
    if (threadIdx.x < 32) {
        int ph = 0, pt = 0;
        for (int k = threadIdx.x; k < b; k += 32) { ph += g_bsumh[k]; pt += g_bsumt[k]; }
#pragma unroll
        for (int o = 16; o; o >>= 1) {
            ph += __shfl_xor_sync(0xFFFFFFFFu, ph, o);
            pt += __shfl_xor_sync(0xFFFFFFFFu, pt, o);
        }
        if (threadIdx.x == 0) { basep[0] = ph; basep[1] = pt; }
    }
    __syncthreads();

    if (i < nE) {
        int oh = basep[0] + exh;
        int ot = basep[1] + ext;
        g_offh[i] = oh; g_curh[i] = oh;
        g_offt[i] = ot; g_curt[i] = ot;
    }
}

// ---------------- K3: fill CSR slots with (rel, ex) — exp computed inline ----------------
__global__ void k_fill(const int* __restrict__ ei,
                       const int* __restrict__ rel, int E) {
    int e = blockIdx.x * blockDim.x + threadIdx.x;
    if (e >= E) return;
    int h = ei[e];
    int t = ei[E + e];
    int r = rel[e];
    float sr = g_sr[r];
    float M = dec_f(g_Menc);
    float sh = g_seh[h], st = g_set[t];
    // B(n) = leaky(s_n + M) >= leaky(s_n + sr) for all r (monotone); exp arg <= 0.
    float exh = __expf(leaky(sh + sr) - leaky(sh + M));
    float ext = __expf(leaky(st + sr) - leaky(st + M));
    int p = atomicAdd(&g_curh[h], 1);
    g_adjh[p] = make_int2(r, __float_as_int(exh));
    int q = atomicAdd(&g_curt[t], 1);
    g_adjt[q] = make_int2(r, __float_as_int(ext));
}

// ---------------- K4: half-warp-split gather (head=lanes 0-15, tail=lanes 16-31) ----------------
__global__ void k_gather(const float* __restrict__ xr,
                         float* __restrict__ out, int nE) {
    int n = (blockIdx.x * blockDim.x + threadIdx.x) >> 5;
    int lane = threadIdx.x & 31;
    if (n >= nE) return;

    bool isHead = lane < 16;
    int k = lane & 15;                       // float4 index within the 64-dim row

    int degh = g_cnth[n], bh = g_offh[n];
    int degt = g_cntt[n], bt = g_offt[n];
    int deg  = isHead ? degh : degt;
    int base = isHead ? bh : bt;
    const int2* adj = isHead ? g_adjh : g_adjt;
    int dmax = max(degh, degt);

    float4 acc = make_float4(0.f, 0.f, 0.f, 0.f);
    float den = 0.f;
    const float4* xr4 = reinterpret_cast<const float4*>(xr);

    for (int j = 0; j < dmax; j++) {
        if (j < deg) {
            int2 arp = adj[base + j];        // uniform within each half-warp
            float w = __int_as_float(arp.y);
            den += w;
            float4 m = xr4[arp.x * (RH / 4) + k];
            acc.x = fmaf(w, m.x, acc.x);
            acc.y = fmaf(w, m.y, acc.y);
            acc.z = fmaf(w, m.z, acc.z);
            acc.w = fmaf(w, m.w, acc.w);
        }
    }

    float inv = (den > 0.f) ? 1.0f / den : 0.f;
    float4* o4 = reinterpret_cast<float4*>(out + (size_t)n * (2 * RH));
    // head half writes float4 slots 0..15 (dims [0,64)), tail half slots 16..31 (dims [64,128))
    o4[lane] = make_float4(acc.x * inv, acc.y * inv, acc.z * inv, acc.w * inv);
}

// ---------------- launch ----------------
extern "C" void kernel_launch(void* const* d_in, const int* in_sizes, int n_in,
                              void* d_out, int out_size) {
    const float* xe  = (const float*)d_in[0];
    const float* xr  = (const float*)d_in[1];
    const int*   ei  = (const int*)d_in[2];   // int32 (JAX x64 disabled)
    const int*   rel = (const int*)d_in[3];
    // d_in[4], d_in[5] (line graph) unused by the reference output
    const float* ahw = (const float*)d_in[6];
    const float* atw = (const float*)d_in[7];
    const float* arw = (const float*)d_in[8];

    int nE = in_sizes[0] / EH;   // 50000
    int nR = in_sizes[1] / RH;   // 1000
    int E  = in_sizes[3];        // 800000
    if (nE > MAX_NE) nE = MAX_NE;
    if (nR > MAX_NR) nR = MAX_NR;
    if (E  > MAX_E)  E  = MAX_E;

    float* out = (float*)d_out;

    int nodeBlocks = (nE + 7) / 8;
    int relBlocks  = (nR + 7) / 8;
    int histBlocks = (E + 255) / 256;
    int nB = (nE + SCAN_B - 1) / SCAN_B;   // 98 <= 148 SMs (single wave, barrier safe)

    k_init<<<(nE + 255) / 256, 256>>>(nE);
    k_phase1<<<nodeBlocks + relBlocks + histBlocks, 256>>>(
        xe, xr, ahw, atw, arw, ei, nE, nR, E, nodeBlocks, relBlocks);
    k_scan<<<nB, SCAN_B>>>(nE, nB);
    k_fill<<<(E + 255) / 256, 256>>>(ei, rel, E);
    k_gather<<<(nE + 7) / 8, 256>>>(xr, out, nE);
}